// round 5
// baseline (speedup 1.0000x reference)
#include <cuda_runtime.h>
#include <stdint.h>

#define Bb 8
#define NF 128
#define Ee 3072
#define Uu 4096
#define UT 64
#define NTHREADS 256
#define LISTCAP 512
#define STAGE_ROWS 128
#define NSTAGES (Ee / STAGE_ROWS)    // 24

// Scratch (static __device__ arrays; no allocation at runtime)
__device__ unsigned short g_vlist[Bb * Ee];                 // v index of e-th true dst slot
__device__ float g_ft[(size_t)Bb * Ee * NF];                // transposed features [b][e][n]

// ---------------- pre-pass 1: transpose features [B,NF,E] -> g_ft [B,E,NF] ----------------
__global__ void transpose_kernel(const float* __restrict__ features) {
    __shared__ float tile[32][33];
    int b  = blockIdx.z;
    int e0 = blockIdx.x * 32;
    int n0 = blockIdx.y * 32;
    int tx = threadIdx.x, ty = threadIdx.y;   // 32 x 8
    const float* src = features + (size_t)b * NF * Ee;
#pragma unroll
    for (int j = 0; j < 32; j += 8)
        tile[ty + j][tx] = src[(size_t)(n0 + ty + j) * Ee + e0 + tx];
    __syncthreads();
    float* dstp = g_ft + (size_t)b * Ee * NF;
#pragma unroll
    for (int j = 0; j < 32; j += 8)
        dstp[(size_t)(e0 + ty + j) * NF + n0 + tx] = tile[tx][ty + j];
}

// ---------------- pre-pass 2: prefix-scan dst mask -> g_vlist (dtype-adaptive) ----------------
__global__ void build_vlist_kernel(const unsigned char* __restrict__ dstraw) {
    __shared__ int s_nz;
    __shared__ int wsum[32];
    int b = blockIdx.x;
    int t = threadIdx.x;                       // 1024 threads, 4 elems each

    if (t == 0) s_nz = 0;
    __syncthreads();
    int nz = (dstraw[t] != 0) + (dstraw[1024 + t] != 0) +
             (dstraw[2048 + t] != 0) + (dstraw[3072 + t] != 0);
#pragma unroll
    for (int off = 16; off; off >>= 1) nz += __shfl_down_sync(0xffffffffu, nz, off);
    if ((t & 31) == 0) atomicAdd(&s_nz, nz);
    __syncthreads();
    bool is_byte = (s_nz > 2048);

    int v0 = t * 4;
    int c0, c1, c2, c3;
    if (is_byte) {
        uchar4 m = *(const uchar4*)(dstraw + (size_t)b * Uu + v0);
        c0 = (m.x != 0); c1 = (m.y != 0); c2 = (m.z != 0); c3 = (m.w != 0);
    } else {
        const uint32_t* d32 = (const uint32_t*)dstraw;
        uint4 m = *(const uint4*)(d32 + (size_t)b * Uu + v0);
        c0 = (m.x != 0); c1 = (m.y != 0); c2 = (m.z != 0); c3 = (m.w != 0);
    }

    int c = c0 + c1 + c2 + c3;
    int incl = c;
#pragma unroll
    for (int off = 1; off < 32; off <<= 1) {
        int y = __shfl_up_sync(0xffffffffu, incl, off);
        if ((t & 31) >= off) incl += y;
    }
    if ((t & 31) == 31) wsum[t >> 5] = incl;
    __syncthreads();
    if (t < 32) {
        int s = wsum[t];
#pragma unroll
        for (int off = 1; off < 32; off <<= 1) {
            int y = __shfl_up_sync(0xffffffffu, s, off);
            if (t >= off) s += y;
        }
        wsum[t] = s;
    }
    __syncthreads();
    int base = (t >= 32) ? wsum[(t >> 5) - 1] : 0;
    int e = base + incl - c;
    if (c0 && e < Ee) g_vlist[b * Ee + e++] = (unsigned short)(v0);
    if (c1 && e < Ee) g_vlist[b * Ee + e++] = (unsigned short)(v0 + 1);
    if (c2 && e < Ee) g_vlist[b * Ee + e++] = (unsigned short)(v0 + 2);
    if (c3 && e < Ee) g_vlist[b * Ee + e++] = (unsigned short)(v0 + 3);
}

// ---------------- main: cp.async-pipelined sparse scan + rank-1 accumulate ----------------
// dynamic smem layout (bytes):
#define OFF_STAGE 0                                   // float[2][STAGE_ROWS*64] = 65536
#define OFF_ACC   65536                               // float[UT*132] = 33792
#define OFF_VL    (OFF_ACC + 33792)                   // ushort[Ee] = 6144
#define OFF_LIST  (OFF_VL + 6144)                     // uint2[LISTCAP] = 4096
#define OFF_OCC   (OFF_LIST + 4096)                   // float[UT] = 256
#define OFF_CNT   (OFF_OCC + 256)                     // int
#define DSMEM_TOTAL (OFF_CNT + 16)

__device__ __forceinline__ uint32_t smem_u32(const void* p) {
    return (uint32_t)__cvta_generic_to_shared(p);
}

__global__ __launch_bounds__(NTHREADS) void unpool_kernel(
    const float* __restrict__ W, const float* __restrict__ occ, float* __restrict__ out) {
    extern __shared__ char dyn[];
    float*          s_stage = (float*)(dyn + OFF_STAGE);
    float*          s_acc   = (float*)(dyn + OFF_ACC);
    unsigned short* s_vl    = (unsigned short*)(dyn + OFF_VL);
    uint2*          s_list  = (uint2*)(dyn + OFF_LIST);
    float*          s_occ   = (float*)(dyn + OFF_OCC);
    int*            s_cnt   = (int*)(dyn + OFF_CNT);

    int b   = blockIdx.y;
    int u0  = blockIdx.x * UT;
    int tid = threadIdx.x;

    for (int i = tid; i < UT * 132; i += NTHREADS) s_acc[i] = 0.f;
    {
        const uint32_t* src = (const uint32_t*)(g_vlist + b * Ee);
        uint32_t* dst = (uint32_t*)s_vl;
        for (int i = tid; i < Ee / 2; i += NTHREADS) dst[i] = src[i];
    }
    if (tid == 0) *s_cnt = 0;
    if (tid < UT) s_occ[tid] = occ[(size_t)b * Uu + u0 + tid];
    __syncthreads();

    const float* Wb = W + (size_t)b * Uu * Uu + u0;
    int g = tid >> 4;          // row group 0..15
    int q = tid & 15;          // float4 slot within 64-wide row segment
    const float* basep = Wb + q * 4;

    // per-thread smem slots: rows (g*8+r) of the stage, 16 bytes at column q*16
    uint32_t my_stage_u32 = smem_u32(s_stage) + (uint32_t)((g * 8) * 64 + q * 4) * 4u;

    // ---- prefetch issue for stage s (8x cp.async 16B, no barrier needed:
    //      each thread loads exactly the bytes it will later scan) ----
#define ISSUE_STAGE(s)                                                          \
    {                                                                           \
        int _buf = (s) & 1;                                                     \
        uint32_t _dst = my_stage_u32 + (uint32_t)(_buf * STAGE_ROWS * 64 * 4);  \
        int _e0 = (s) * STAGE_ROWS + g * 8;                                     \
        _Pragma("unroll")                                                       \
        for (int _r = 0; _r < 8; ++_r) {                                        \
            const float* _src = basep + (size_t)s_vl[_e0 + _r] * Uu;            \
            asm volatile("cp.async.ca.shared.global [%0], [%1], 16;"            \
                         :: "r"(_dst + (uint32_t)(_r * 64 * 4)), "l"(_src));    \
        }                                                                       \
        asm volatile("cp.async.commit_group;" ::: "memory");                    \
    }

    ISSUE_STAGE(0);
    for (int s = 0; s < NSTAGES; ++s) {
        if (s + 1 < NSTAGES) {
            ISSUE_STAGE(s + 1);
            asm volatile("cp.async.wait_group 1;" ::: "memory");
        } else {
            asm volatile("cp.async.wait_group 0;" ::: "memory");
        }
        // ---- scan stage s from smem ----
        int buf = s & 1;
        const float* sp = s_stage + buf * STAGE_ROWS * 64 + (g * 8) * 64 + q * 4;
        float4 xs[8];
#pragma unroll
        for (int r = 0; r < 8; ++r)
            xs[r] = *(const float4*)(sp + r * 64);

#define ORW(v4) (__float_as_uint((v4).x) | __float_as_uint((v4).y) | \
                 __float_as_uint((v4).z) | __float_as_uint((v4).w))
        unsigned any = (ORW(xs[0]) | ORW(xs[1]) | ORW(xs[2]) | ORW(xs[3])) |
                       (ORW(xs[4]) | ORW(xs[5]) | ORW(xs[6]) | ORW(xs[7]));
        if (any) {
            int e0 = s * STAGE_ROWS + g * 8;
#pragma unroll
            for (int r = 0; r < 8; ++r) {
                int e = e0 + r;
                float vals[4] = {xs[r].x, xs[r].y, xs[r].z, xs[r].w};
#pragma unroll
                for (int k = 0; k < 4; ++k) {
                    if (__float_as_uint(vals[k]) != 0u) {
                        int p = atomicAdd(s_cnt, 1);
                        if (p < LISTCAP)
                            s_list[p] = make_uint2(((unsigned)e << 6) | (unsigned)(q * 4 + k),
                                                   __float_as_uint(vals[k]));
                    }
                }
            }
        }
    }

    // ---- single flush (expected cnt ~137 << LISTCAP) ----
    __syncthreads();
    int cnt = min(*s_cnt, LISTCAP);
    {
        int warp = tid >> 5;     // 0..7
        int lane = tid & 31;
        int n0 = lane * 4;
        if (cnt > 0) {
            // software pipeline: prefetch entry/feature for j+1 while applying j
            uint2 ent = s_list[0];
            float4 f4 = *(const float4*)&g_ft[((size_t)b * Ee + (ent.x >> 6)) * NF + n0];
            for (int j = 0; j < cnt; ++j) {
                uint2 ent_n;
                float4 f4_n;
                if (j + 1 < cnt) {
                    ent_n = s_list[j + 1];
                    f4_n = *(const float4*)&g_ft[((size_t)b * Ee + (ent_n.x >> 6)) * NF + n0];
                }
                int u = ent.x & 63;
                if ((u & 7) == warp) {       // disjoint u-classes: no RMW races
                    float w = __uint_as_float(ent.y);
                    float4* ap = (float4*)&s_acc[u * 132 + n0];
                    float4 a = *ap;
                    a.x += w * f4.x; a.y += w * f4.y; a.z += w * f4.z; a.w += w * f4.w;
                    *ap = a;
                }
                ent = ent_n;
                f4 = f4_n;
            }
        }
    }
    __syncthreads();

    // ---- epilogue: divide by occurrences, coalesced store ----
    int u = tid & (UT - 1);
    int nb = tid >> 6;          // 0..3
#pragma unroll
    for (int i = 0; i < (UT * NF / NTHREADS); ++i) {  // 32 iters
        int n = 4 * i + nb;
        out[((size_t)(b * NF + n)) * Uu + u0 + u] = s_acc[u * 132 + n] / s_occ[u];
    }
}

extern "C" void kernel_launch(void* const* d_in, const int* in_sizes, int n_in,
                              void* d_out, int out_size) {
    const float* features          = (const float*)d_in[0];
    const float* unroll_mat        = (const float*)d_in[1];
    const float* occurrences       = (const float*)d_in[2];
    const unsigned char* dst_masks = (const unsigned char*)d_in[3];
    float* out = (float*)d_out;

    static bool configured = false;
    if (!configured) {
        cudaFuncSetAttribute(unpool_kernel,
                             cudaFuncAttributeMaxDynamicSharedMemorySize, DSMEM_TOTAL);
        configured = true;
    }

    dim3 tg(Ee / 32, NF / 32, Bb);
    transpose_kernel<<<tg, dim3(32, 8)>>>(features);
    build_vlist_kernel<<<Bb, 1024>>>(dst_masks);
    dim3 mg(Uu / UT, Bb);
    unpool_kernel<<<mg, NTHREADS, DSMEM_TOTAL>>>(unroll_mat, occurrences, out);
}

// round 6
// speedup vs baseline: 1.7075x; 1.7075x over previous
#include <cuda_runtime.h>
#include <stdint.h>

#define Bb 8
#define NF 128
#define Ee 3072
#define Uu 4096
#define UT 64
#define NTILES (Uu / UT)          // 64
#define TCAP 512

// Scratch (static __device__ arrays; no allocation at runtime)
__device__ unsigned short g_vlist[Bb * Ee];                 // v index of e-th true dst slot
__device__ float g_ft[(size_t)Bb * Ee * NF];                // transposed features [b][e][n]
__device__ int   g_cnt[Bb * NTILES];                        // per-(b,utile) hit counts
__device__ uint2 g_list[(size_t)Bb * NTILES * TCAP];        // hit entries: (e<<6|ulocal, w bits)

// ---------------- pre-pass 1: transpose features [B,NF,E] -> g_ft [B,E,NF] ----------------
__global__ void transpose_kernel(const float* __restrict__ features) {
    __shared__ float tile[32][33];
    int b  = blockIdx.z;
    int e0 = blockIdx.x * 32;
    int n0 = blockIdx.y * 32;
    int tx = threadIdx.x, ty = threadIdx.y;   // 32 x 8
    const float* src = features + (size_t)b * NF * Ee;
#pragma unroll
    for (int j = 0; j < 32; j += 8)
        tile[ty + j][tx] = src[(size_t)(n0 + ty + j) * Ee + e0 + tx];
    __syncthreads();
    float* dstp = g_ft + (size_t)b * Ee * NF;
#pragma unroll
    for (int j = 0; j < 32; j += 8)
        dstp[(size_t)(e0 + ty + j) * NF + n0 + tx] = tile[tx][ty + j];
}

// ---------------- pre-pass 2: prefix-scan dst mask -> g_vlist; zero hit counters ----------------
__global__ void build_vlist_kernel(const unsigned char* __restrict__ dstraw) {
    __shared__ int s_nz;
    __shared__ int wsum[32];
    int b = blockIdx.x;
    int t = threadIdx.x;                       // 1024 threads, 4 elems each

    if (t < NTILES) g_cnt[b * NTILES + t] = 0;  // reset counters every call (graph-safe)

    // --- dtype detection: nonzero bytes among first 4096 bytes of the buffer ---
    if (t == 0) s_nz = 0;
    __syncthreads();
    int nz = (dstraw[t] != 0) + (dstraw[1024 + t] != 0) +
             (dstraw[2048 + t] != 0) + (dstraw[3072 + t] != 0);
#pragma unroll
    for (int off = 16; off; off >>= 1) nz += __shfl_down_sync(0xffffffffu, nz, off);
    if ((t & 31) == 0) atomicAdd(&s_nz, nz);
    __syncthreads();
    bool is_byte = (s_nz > 2048);

    int v0 = t * 4;
    int c0, c1, c2, c3;
    if (is_byte) {
        uchar4 m = *(const uchar4*)(dstraw + (size_t)b * Uu + v0);
        c0 = (m.x != 0); c1 = (m.y != 0); c2 = (m.z != 0); c3 = (m.w != 0);
    } else {
        const uint32_t* d32 = (const uint32_t*)dstraw;
        uint4 m = *(const uint4*)(d32 + (size_t)b * Uu + v0);
        c0 = (m.x != 0); c1 = (m.y != 0); c2 = (m.z != 0); c3 = (m.w != 0);
    }

    int c = c0 + c1 + c2 + c3;
    int incl = c;
#pragma unroll
    for (int off = 1; off < 32; off <<= 1) {
        int y = __shfl_up_sync(0xffffffffu, incl, off);
        if ((t & 31) >= off) incl += y;
    }
    if ((t & 31) == 31) wsum[t >> 5] = incl;
    __syncthreads();
    if (t < 32) {
        int s = wsum[t];
#pragma unroll
        for (int off = 1; off < 32; off <<= 1) {
            int y = __shfl_up_sync(0xffffffffu, s, off);
            if (t >= off) s += y;
        }
        wsum[t] = s;
    }
    __syncthreads();
    int base = (t >= 32) ? wsum[(t >> 5) - 1] : 0;
    int e = base + incl - c;
    if (c0 && e < Ee) g_vlist[b * Ee + e++] = (unsigned short)(v0);
    if (c1 && e < Ee) g_vlist[b * Ee + e++] = (unsigned short)(v0 + 1);
    if (c2 && e < Ee) g_vlist[b * Ee + e++] = (unsigned short)(v0 + 2);
    if (c3 && e < Ee) g_vlist[b * Ee + e++] = (unsigned short)(v0 + 3);
}

// ---------------- scan: one warp streams one full 16KB row of W, emits hits ----------------
__global__ __launch_bounds__(256) void scan_kernel(const float* __restrict__ W) {
    int b    = blockIdx.y;
    int warp = threadIdx.x >> 5;
    int lane = threadIdx.x & 31;
    int e    = blockIdx.x * 8 + warp;

    int v = g_vlist[b * Ee + e];
    const float4* row = (const float4*)(W + ((size_t)b * Uu + v) * Uu);

#pragma unroll 1
    for (int i0 = 0; i0 < 32; i0 += 8) {
        float4 x[8];
#pragma unroll
        for (int j = 0; j < 8; ++j)
            x[j] = row[(i0 + j) * 32 + lane];

#define ORW(v4) (__float_as_uint((v4).x) | __float_as_uint((v4).y) | \
                 __float_as_uint((v4).z) | __float_as_uint((v4).w))
        unsigned any = (ORW(x[0]) | ORW(x[1]) | ORW(x[2]) | ORW(x[3])) |
                       (ORW(x[4]) | ORW(x[5]) | ORW(x[6]) | ORW(x[7]));
        if (any) {
#pragma unroll
            for (int j = 0; j < 8; ++j) {
                float vals[4] = {x[j].x, x[j].y, x[j].z, x[j].w};
#pragma unroll
                for (int k = 0; k < 4; ++k) {
                    if (__float_as_uint(vals[k]) != 0u) {
                        int u  = ((i0 + j) * 32 + lane) * 4 + k;
                        int ut = u >> 6;
                        int pos = atomicAdd(&g_cnt[b * NTILES + ut], 1);
                        if (pos < TCAP)
                            g_list[((size_t)(b * NTILES + ut)) * TCAP + pos] =
                                make_uint2(((unsigned)e << 6) | (unsigned)(u & 63),
                                           __float_as_uint(vals[k]));
                    }
                }
            }
        }
    }
}

// ---------------- accumulate: drain per-tile lists into smem acc, divide, store ----------------
__global__ __launch_bounds__(256) void accum_kernel(
    const float* __restrict__ occ, float* __restrict__ out) {
    __shared__ float s_acc[UT * 132];
    __shared__ float s_occ[UT];

    int b   = blockIdx.y;
    int ut  = blockIdx.x;
    int u0  = ut * UT;
    int tid = threadIdx.x;
    int warp = tid >> 5;     // 0..7
    int lane = tid & 31;
    int n0 = lane * 4;

    for (int i = tid; i < UT * 132; i += 256) s_acc[i] = 0.f;
    if (tid < UT) s_occ[tid] = occ[(size_t)b * Uu + u0 + tid];
    __syncthreads();

    int cnt = min(g_cnt[b * NTILES + ut], TCAP);
    const uint2* list = &g_list[((size_t)(b * NTILES + ut)) * TCAP];

    if (cnt > 0) {
        uint2 ent = __ldg(&list[0]);
        for (int j = 0; j < cnt; ++j) {
            uint2 ent_n;
            if (j + 1 < cnt) ent_n = __ldg(&list[j + 1]);
            int u = ent.x & 63;
            if ((u & 7) == warp) {           // disjoint u-classes: no RMW races
                int e = ent.x >> 6;
                float w = __uint_as_float(ent.y);
                const float4 f4 = *(const float4*)&g_ft[((size_t)b * Ee + e) * NF + n0];
                float4* ap = (float4*)&s_acc[u * 132 + n0];
                float4 a = *ap;
                a.x += w * f4.x; a.y += w * f4.y; a.z += w * f4.z; a.w += w * f4.w;
                *ap = a;
            }
            ent = ent_n;
        }
    }
    __syncthreads();

    // epilogue: divide by occurrences, coalesced store
    int u  = tid & (UT - 1);
    int nb = tid >> 6;          // 0..3
#pragma unroll
    for (int i = 0; i < (UT * NF / 256); ++i) {   // 32 iters
        int n = 4 * i + nb;
        out[((size_t)(b * NF + n)) * Uu + u0 + u] = s_acc[u * 132 + n] / s_occ[u];
    }
}

extern "C" void kernel_launch(void* const* d_in, const int* in_sizes, int n_in,
                              void* d_out, int out_size) {
    const float* features          = (const float*)d_in[0];
    const float* unroll_mat        = (const float*)d_in[1];
    const float* occurrences       = (const float*)d_in[2];
    const unsigned char* dst_masks = (const unsigned char*)d_in[3];
    float* out = (float*)d_out;

    build_vlist_kernel<<<Bb, 1024>>>(dst_masks);
    scan_kernel<<<dim3(Ee / 8, Bb), 256>>>(unroll_mat);
    dim3 tg(Ee / 32, NF / 32, Bb);
    transpose_kernel<<<tg, dim3(32, 8)>>>(features);
    accum_kernel<<<dim3(NTILES, Bb), 256>>>(occurrences, out);
}

// round 7
// speedup vs baseline: 2.0374x; 1.1932x over previous
#include <cuda_runtime.h>
#include <stdint.h>

#define Bb 8
#define NF 128
#define Ee 3072
#define Uu 4096
#define UT 64
#define NTILES (Uu / UT)          // 64
#define TCAP 512

// Scratch (static __device__ arrays; no allocation at runtime)
__device__ unsigned short g_vlist[Bb * Ee];                 // v index of e-th true dst slot
__device__ float g_ft[(size_t)Bb * Ee * NF];                // transposed features [b][e][n]
__device__ int   g_cnt[Bb * NTILES];                        // per-(b,utile) hit counts
__device__ uint2 g_list[(size_t)Bb * NTILES * TCAP];        // hit entries: (e<<6|ulocal, w bits)

// ---------------- pre-pass 1: transpose features [B,NF,E] -> g_ft [B,E,NF] ----------------
__global__ void transpose_kernel(const float* __restrict__ features) {
    __shared__ float tile[32][33];
    int b  = blockIdx.z;
    int e0 = blockIdx.x * 32;
    int n0 = blockIdx.y * 32;
    int tx = threadIdx.x, ty = threadIdx.y;   // 32 x 8
    const float* src = features + (size_t)b * NF * Ee;
#pragma unroll
    for (int j = 0; j < 32; j += 8)
        tile[ty + j][tx] = src[(size_t)(n0 + ty + j) * Ee + e0 + tx];
    __syncthreads();
    float* dstp = g_ft + (size_t)b * Ee * NF;
#pragma unroll
    for (int j = 0; j < 32; j += 8)
        dstp[(size_t)(e0 + ty + j) * NF + n0 + tx] = tile[tx][ty + j];
}

// ---------------- pre-pass 2: prefix-scan dst mask -> g_vlist; zero hit counters ----------------
__global__ void build_vlist_kernel(const unsigned char* __restrict__ dstraw) {
    __shared__ int s_nz;
    __shared__ int wsum[32];
    int b = blockIdx.x;
    int t = threadIdx.x;                       // 1024 threads, 4 elems each

    if (t < NTILES) g_cnt[b * NTILES + t] = 0;  // reset counters every call (graph-safe)

    // --- dtype detection: nonzero bytes among first 4096 bytes of the buffer ---
    if (t == 0) s_nz = 0;
    __syncthreads();
    int nz = (dstraw[t] != 0) + (dstraw[1024 + t] != 0) +
             (dstraw[2048 + t] != 0) + (dstraw[3072 + t] != 0);
#pragma unroll
    for (int off = 16; off; off >>= 1) nz += __shfl_down_sync(0xffffffffu, nz, off);
    if ((t & 31) == 0) atomicAdd(&s_nz, nz);
    __syncthreads();
    bool is_byte = (s_nz > 2048);

    int v0 = t * 4;
    int c0, c1, c2, c3;
    if (is_byte) {
        uchar4 m = *(const uchar4*)(dstraw + (size_t)b * Uu + v0);
        c0 = (m.x != 0); c1 = (m.y != 0); c2 = (m.z != 0); c3 = (m.w != 0);
    } else {
        const uint32_t* d32 = (const uint32_t*)dstraw;
        uint4 m = *(const uint4*)(d32 + (size_t)b * Uu + v0);
        c0 = (m.x != 0); c1 = (m.y != 0); c2 = (m.z != 0); c3 = (m.w != 0);
    }

    int c = c0 + c1 + c2 + c3;
    int incl = c;
#pragma unroll
    for (int off = 1; off < 32; off <<= 1) {
        int y = __shfl_up_sync(0xffffffffu, incl, off);
        if ((t & 31) >= off) incl += y;
    }
    if ((t & 31) == 31) wsum[t >> 5] = incl;
    __syncthreads();
    if (t < 32) {
        int s = wsum[t];
#pragma unroll
        for (int off = 1; off < 32; off <<= 1) {
            int y = __shfl_up_sync(0xffffffffu, s, off);
            if (t >= off) s += y;
        }
        wsum[t] = s;
    }
    __syncthreads();
    int base = (t >= 32) ? wsum[(t >> 5) - 1] : 0;
    int e = base + incl - c;
    if (c0 && e < Ee) g_vlist[b * Ee + e++] = (unsigned short)(v0);
    if (c1 && e < Ee) g_vlist[b * Ee + e++] = (unsigned short)(v0 + 1);
    if (c2 && e < Ee) g_vlist[b * Ee + e++] = (unsigned short)(v0 + 2);
    if (c3 && e < Ee) g_vlist[b * Ee + e++] = (unsigned short)(v0 + 3);
}

// ---------------- scan: one warp streams one full 16KB row of W, emits hits ----------------
__global__ __launch_bounds__(256) void scan_kernel(const float* __restrict__ W) {
    int b    = blockIdx.y;
    int warp = threadIdx.x >> 5;
    int lane = threadIdx.x & 31;
    int e    = blockIdx.x * 8 + warp;

    int v = g_vlist[b * Ee + e];
    const float4* row = (const float4*)(W + ((size_t)b * Uu + v) * Uu);

#pragma unroll 1
    for (int i0 = 0; i0 < 32; i0 += 8) {
        float4 x[8];
#pragma unroll
        for (int j = 0; j < 8; ++j)
            x[j] = __ldcs(&row[(i0 + j) * 32 + lane]);   // streaming: read-once data

#define ORW(v4) (__float_as_uint((v4).x) | __float_as_uint((v4).y) | \
                 __float_as_uint((v4).z) | __float_as_uint((v4).w))
        unsigned any = (ORW(x[0]) | ORW(x[1]) | ORW(x[2]) | ORW(x[3])) |
                       (ORW(x[4]) | ORW(x[5]) | ORW(x[6]) | ORW(x[7]));
        if (any) {
#pragma unroll
            for (int j = 0; j < 8; ++j) {
                float vals[4] = {x[j].x, x[j].y, x[j].z, x[j].w};
#pragma unroll
                for (int k = 0; k < 4; ++k) {
                    if (__float_as_uint(vals[k]) != 0u) {
                        int u  = ((i0 + j) * 32 + lane) * 4 + k;
                        int ut = u >> 6;
                        int pos = atomicAdd(&g_cnt[b * NTILES + ut], 1);
                        if (pos < TCAP)
                            g_list[((size_t)(b * NTILES + ut)) * TCAP + pos] =
                                make_uint2(((unsigned)e << 6) | (unsigned)(u & 63),
                                           __float_as_uint(vals[k]));
                    }
                }
            }
        }
    }
}

// ---------------- accumulate: drain per-tile lists via smem float atomics ----------------
__global__ __launch_bounds__(256) void accum_kernel(
    const float* __restrict__ occ, float* __restrict__ out) {
    __shared__ float s_acc[UT * 132];
    __shared__ float s_rocc[UT];

    int b   = blockIdx.y;
    int ut  = blockIdx.x;
    int u0  = ut * UT;
    int tid = threadIdx.x;
    int warp = tid >> 5;     // 0..7
    int lane = tid & 31;
    int n0 = lane * 4;

    for (int i = tid; i < UT * 132; i += 256) s_acc[i] = 0.f;
    if (tid < UT) s_rocc[tid] = 1.0f / occ[(size_t)b * Uu + u0 + tid];
    __syncthreads();

    int cnt = min(g_cnt[b * NTILES + ut], TCAP);
    const uint2* list = &g_list[((size_t)(b * NTILES + ut)) * TCAP];

    // warp w handles entries w, w+8, w+16, ... ; races on same u resolved by smem atomics.
    // (fp-add order varies at ULP level only: sums have <=5 terms)
    for (int j = warp; j < cnt; j += 8) {
        uint2 ent = __ldg(&list[j]);
        // prefetch next entry early
        uint2 ent_n = make_uint2(0u, 0u);
        int jn = j + 8;
        if (jn < cnt) ent_n = __ldg(&list[jn]);
        for (;;) {
            int u = ent.x & 63;
            float w = __uint_as_float(ent.y);
            const float4 f4 = *(const float4*)&g_ft[((size_t)b * Ee + (ent.x >> 6)) * NF + n0];
            float* ap = &s_acc[u * 132 + n0];
            atomicAdd(ap + 0, w * f4.x);
            atomicAdd(ap + 1, w * f4.y);
            atomicAdd(ap + 2, w * f4.z);
            atomicAdd(ap + 3, w * f4.w);
            break;
        }
        (void)ent_n;  // compiler keeps the prefetch load alive via next iteration's __ldg
    }
    __syncthreads();

    // epilogue: multiply by 1/occ, coalesced store
    int u  = tid & (UT - 1);
    int nb = tid >> 6;          // 0..3
    float r = s_rocc[u];
#pragma unroll
    for (int i = 0; i < (UT * NF / 256); ++i) {   // 32 iters
        int n = 4 * i + nb;
        out[((size_t)(b * NF + n)) * Uu + u0 + u] = s_acc[u * 132 + n] * r;
    }
}

extern "C" void kernel_launch(void* const* d_in, const int* in_sizes, int n_in,
                              void* d_out, int out_size) {
    const float* features          = (const float*)d_in[0];
    const float* unroll_mat        = (const float*)d_in[1];
    const float* occurrences       = (const float*)d_in[2];
    const unsigned char* dst_masks = (const unsigned char*)d_in[3];
    float* out = (float*)d_out;

    build_vlist_kernel<<<Bb, 1024>>>(dst_masks);
    scan_kernel<<<dim3(Ee / 8, Bb), 256>>>(unroll_mat);
    dim3 tg(Ee / 32, NF / 32, Bb);
    transpose_kernel<<<tg, dim3(32, 8)>>>(features);
    accum_kernel<<<dim3(NTILES, Bb), 256>>>(occurrences, out);
}

// round 8
// speedup vs baseline: 2.0814x; 1.0216x over previous
#include <cuda_runtime.h>
#include <stdint.h>

#define Bb 8
#define NF 128
#define Ee 3072
#define Uu 4096
#define UT 64
#define NTILES (Uu / UT)          // 64
#define TCAP 512

// Scratch (static __device__ arrays; no allocation at runtime)
__device__ unsigned short g_vlist[Bb * Ee];                 // v index of e-th true dst slot
__device__ float g_ft[(size_t)Bb * Ee * NF];                // transposed features [b][e][n]
__device__ int   g_cnt[Bb * NTILES];                        // per-(b,utile) hit counts
__device__ uint2 g_list[(size_t)Bb * NTILES * TCAP];        // hit entries: (e<<6|ulocal, w bits)

// ---------------- pre-pass 1: transpose features [B,NF,E] -> g_ft [B,E,NF] ----------------
__global__ void transpose_kernel(const float* __restrict__ features) {
    __shared__ float tile[32][33];
    int b  = blockIdx.z;
    int e0 = blockIdx.x * 32;
    int n0 = blockIdx.y * 32;
    int tx = threadIdx.x, ty = threadIdx.y;   // 32 x 8
    const float* src = features + (size_t)b * NF * Ee;
#pragma unroll
    for (int j = 0; j < 32; j += 8)
        tile[ty + j][tx] = src[(size_t)(n0 + ty + j) * Ee + e0 + tx];
    __syncthreads();
    float* dstp = g_ft + (size_t)b * Ee * NF;
#pragma unroll
    for (int j = 0; j < 32; j += 8)
        dstp[(size_t)(e0 + ty + j) * NF + n0 + tx] = tile[tx][ty + j];
}

// ---------------- pre-pass 2: prefix-scan dst mask -> g_vlist; zero hit counters ----------------
__global__ void build_vlist_kernel(const unsigned char* __restrict__ dstraw) {
    __shared__ int s_nz;
    __shared__ int wsum[32];
    int b = blockIdx.x;
    int t = threadIdx.x;                       // 1024 threads, 4 elems each

    if (t < NTILES) g_cnt[b * NTILES + t] = 0;  // reset counters every call (graph-safe)

    // --- dtype detection: nonzero bytes among first 4096 bytes of the buffer ---
    if (t == 0) s_nz = 0;
    __syncthreads();
    int nz = (dstraw[t] != 0) + (dstraw[1024 + t] != 0) +
             (dstraw[2048 + t] != 0) + (dstraw[3072 + t] != 0);
#pragma unroll
    for (int off = 16; off; off >>= 1) nz += __shfl_down_sync(0xffffffffu, nz, off);
    if ((t & 31) == 0) atomicAdd(&s_nz, nz);
    __syncthreads();
    bool is_byte = (s_nz > 2048);

    int v0 = t * 4;
    int c0, c1, c2, c3;
    if (is_byte) {
        uchar4 m = *(const uchar4*)(dstraw + (size_t)b * Uu + v0);
        c0 = (m.x != 0); c1 = (m.y != 0); c2 = (m.z != 0); c3 = (m.w != 0);
    } else {
        const uint32_t* d32 = (const uint32_t*)dstraw;
        uint4 m = *(const uint4*)(d32 + (size_t)b * Uu + v0);
        c0 = (m.x != 0); c1 = (m.y != 0); c2 = (m.z != 0); c3 = (m.w != 0);
    }

    int c = c0 + c1 + c2 + c3;
    int incl = c;
#pragma unroll
    for (int off = 1; off < 32; off <<= 1) {
        int y = __shfl_up_sync(0xffffffffu, incl, off);
        if ((t & 31) >= off) incl += y;
    }
    if ((t & 31) == 31) wsum[t >> 5] = incl;
    __syncthreads();
    if (t < 32) {
        int s = wsum[t];
#pragma unroll
        for (int off = 1; off < 32; off <<= 1) {
            int y = __shfl_up_sync(0xffffffffu, s, off);
            if (t >= off) s += y;
        }
        wsum[t] = s;
    }
    __syncthreads();
    int base = (t >= 32) ? wsum[(t >> 5) - 1] : 0;
    int e = base + incl - c;
    if (c0 && e < Ee) g_vlist[b * Ee + e++] = (unsigned short)(v0);
    if (c1 && e < Ee) g_vlist[b * Ee + e++] = (unsigned short)(v0 + 1);
    if (c2 && e < Ee) g_vlist[b * Ee + e++] = (unsigned short)(v0 + 2);
    if (c3 && e < Ee) g_vlist[b * Ee + e++] = (unsigned short)(v0 + 3);
}

// ---------------- scan: one warp streams one full 16KB row of W, emits hits ----------------
__global__ __launch_bounds__(256) void scan_kernel(const float* __restrict__ W) {
    int b    = blockIdx.y;
    int warp = threadIdx.x >> 5;
    int lane = threadIdx.x & 31;
    int e    = blockIdx.x * 8 + warp;

    int v = g_vlist[b * Ee + e];
    const float4* row = (const float4*)(W + ((size_t)b * Uu + v) * Uu);

#pragma unroll 1
    for (int i0 = 0; i0 < 32; i0 += 8) {
        float4 x[8];
#pragma unroll
        for (int j = 0; j < 8; ++j)
            x[j] = __ldcs(&row[(i0 + j) * 32 + lane]);   // streaming: read-once data

#define ORW(v4) (__float_as_uint((v4).x) | __float_as_uint((v4).y) | \
                 __float_as_uint((v4).z) | __float_as_uint((v4).w))
        unsigned any = (ORW(x[0]) | ORW(x[1]) | ORW(x[2]) | ORW(x[3])) |
                       (ORW(x[4]) | ORW(x[5]) | ORW(x[6]) | ORW(x[7]));
        if (any) {
#pragma unroll
            for (int j = 0; j < 8; ++j) {
                float vals[4] = {x[j].x, x[j].y, x[j].z, x[j].w};
#pragma unroll
                for (int k = 0; k < 4; ++k) {
                    if (__float_as_uint(vals[k]) != 0u) {
                        int u  = ((i0 + j) * 32 + lane) * 4 + k;
                        int ut = u >> 6;
                        int pos = atomicAdd(&g_cnt[b * NTILES + ut], 1);
                        if (pos < TCAP)
                            g_list[((size_t)(b * NTILES + ut)) * TCAP + pos] =
                                make_uint2(((unsigned)e << 6) | (unsigned)(u & 63),
                                           __float_as_uint(vals[k]));
                    }
                }
            }
        }
    }
}

// ---------------- accumulate: smem-staged entries + 4-wide gather pipeline ----------------
__global__ __launch_bounds__(256) void accum_kernel(
    const float* __restrict__ occ, float* __restrict__ out) {
    __shared__ float s_acc[UT * 132];
    __shared__ float s_rocc[UT];
    __shared__ uint2 s_ent[TCAP];

    int b   = blockIdx.y;
    int ut  = blockIdx.x;
    int u0  = ut * UT;
    int tid = threadIdx.x;
    int warp = tid >> 5;     // 0..7
    int lane = tid & 31;
    int n0 = lane * 4;

    for (int i = tid; i < UT * 132; i += 256) s_acc[i] = 0.f;
    if (tid < UT) s_rocc[tid] = 1.0f / occ[(size_t)b * Uu + u0 + tid];

    int cnt = min(g_cnt[b * NTILES + ut], TCAP);
    const uint2* list = &g_list[((size_t)(b * NTILES + ut)) * TCAP];
    // coalesced staging of the whole entry list into smem
    for (int i = tid; i < cnt; i += 256) s_ent[i] = __ldg(&list[i]);
    __syncthreads();

    const float* ftb = g_ft + (size_t)b * Ee * NF + n0;

    // warp w handles entries w, w+8, ... in chunks of 4 so the 4 feature gathers
    // are independent (MLP=4). Races on same u resolved by smem float atomics
    // (fp-add order varies at ULP level only: sums have <=5 terms).
    for (int j0 = warp; j0 < cnt; j0 += 32) {
        uint2 e0, e1, e2, e3;
        float4 f0, f1, f2, f3;
        int m = 0;
        int j;
        j = j0;          if (j < cnt) { e0 = s_ent[j]; f0 = *(const float4*)__builtin_assume_aligned(&ftb[(size_t)(e0.x >> 6) * NF], 16); m = 1; }
        j = j0 + 8;      if (j < cnt) { e1 = s_ent[j]; f1 = *(const float4*)&ftb[(size_t)(e1.x >> 6) * NF]; m = 2; }
        j = j0 + 16;     if (j < cnt) { e2 = s_ent[j]; f2 = *(const float4*)&ftb[(size_t)(e2.x >> 6) * NF]; m = 3; }
        j = j0 + 24;     if (j < cnt) { e3 = s_ent[j]; f3 = *(const float4*)&ftb[(size_t)(e3.x >> 6) * NF]; m = 4; }

#define APPLY(ee, ff)                                                     \
        {                                                                 \
            int u = (ee).x & 63;                                          \
            float w = __uint_as_float((ee).y);                            \
            float* ap = &s_acc[u * 132 + n0];                             \
            atomicAdd(ap + 0, w * (ff).x);                                \
            atomicAdd(ap + 1, w * (ff).y);                                \
            atomicAdd(ap + 2, w * (ff).z);                                \
            atomicAdd(ap + 3, w * (ff).w);                                \
        }
        if (m > 0) APPLY(e0, f0);
        if (m > 1) APPLY(e1, f1);
        if (m > 2) APPLY(e2, f2);
        if (m > 3) APPLY(e3, f3);
    }
    __syncthreads();

    // epilogue: multiply by 1/occ, coalesced store
    int u  = tid & (UT - 1);
    int nb = tid >> 6;          // 0..3
    float r = s_rocc[u];
#pragma unroll
    for (int i = 0; i < (UT * NF / 256); ++i) {   // 32 iters
        int n = 4 * i + nb;
        out[((size_t)(b * NF + n)) * Uu + u0 + u] = s_acc[u * 132 + n] * r;
    }
}

extern "C" void kernel_launch(void* const* d_in, const int* in_sizes, int n_in,
                              void* d_out, int out_size) {
    const float* features          = (const float*)d_in[0];
    const float* unroll_mat        = (const float*)d_in[1];
    const float* occurrences       = (const float*)d_in[2];
    const unsigned char* dst_masks = (const unsigned char*)d_in[3];
    float* out = (float*)d_out;

    build_vlist_kernel<<<Bb, 1024>>>(dst_masks);
    scan_kernel<<<dim3(Ee / 8, Bb), 256>>>(unroll_mat);
    dim3 tg(Ee / 32, NF / 32, Bb);
    transpose_kernel<<<tg, dim3(32, 8)>>>(features);
    accum_kernel<<<dim3(NTILES, Bb), 256>>>(occurrences, out);
}

// round 9
// speedup vs baseline: 2.3338x; 1.1213x over previous
#include <cuda_runtime.h>
#include <stdint.h>

#define Bb 8
#define NF 128
#define Ee 3072
#define Uu 4096
#define UT 64
#define NTILES (Uu / UT)          // 64
#define TCAP 512
#define BK 128                    // per-class bucket capacity (expected ~17)

// Scratch (static __device__ arrays; no allocation at runtime)
__device__ unsigned short g_vlist[Bb * Ee];                 // v index of e-th true dst slot
__device__ float g_ft[(size_t)Bb * Ee * NF];                // transposed features [b][e][n]
__device__ int   g_cnt[Bb * NTILES];                        // per-(b,utile) hit counts
__device__ uint2 g_list[(size_t)Bb * NTILES * TCAP];        // hit entries: (e<<6|ulocal, w bits)

// ---------------- pre-pass 1: transpose features [B,NF,E] -> g_ft [B,E,NF] ----------------
__global__ void transpose_kernel(const float* __restrict__ features) {
    __shared__ float tile[32][33];
    int b  = blockIdx.z;
    int e0 = blockIdx.x * 32;
    int n0 = blockIdx.y * 32;
    int tx = threadIdx.x, ty = threadIdx.y;   // 32 x 8
    const float* src = features + (size_t)b * NF * Ee;
#pragma unroll
    for (int j = 0; j < 32; j += 8)
        tile[ty + j][tx] = src[(size_t)(n0 + ty + j) * Ee + e0 + tx];
    __syncthreads();
    float* dstp = g_ft + (size_t)b * Ee * NF;
#pragma unroll
    for (int j = 0; j < 32; j += 8)
        dstp[(size_t)(e0 + ty + j) * NF + n0 + tx] = tile[tx][ty + j];
}

// ---------------- pre-pass 2: prefix-scan dst mask -> g_vlist; zero hit counters ----------------
__global__ void build_vlist_kernel(const unsigned char* __restrict__ dstraw) {
    __shared__ int s_nz;
    __shared__ int wsum[32];
    int b = blockIdx.x;
    int t = threadIdx.x;                       // 1024 threads, 4 elems each

    if (t < NTILES) g_cnt[b * NTILES + t] = 0;  // reset counters every call (graph-safe)

    // --- dtype detection: nonzero bytes among first 4096 bytes of the buffer ---
    if (t == 0) s_nz = 0;
    __syncthreads();
    int nz = (dstraw[t] != 0) + (dstraw[1024 + t] != 0) +
             (dstraw[2048 + t] != 0) + (dstraw[3072 + t] != 0);
#pragma unroll
    for (int off = 16; off; off >>= 1) nz += __shfl_down_sync(0xffffffffu, nz, off);
    if ((t & 31) == 0) atomicAdd(&s_nz, nz);
    __syncthreads();
    bool is_byte = (s_nz > 2048);

    int v0 = t * 4;
    int c0, c1, c2, c3;
    if (is_byte) {
        uchar4 m = *(const uchar4*)(dstraw + (size_t)b * Uu + v0);
        c0 = (m.x != 0); c1 = (m.y != 0); c2 = (m.z != 0); c3 = (m.w != 0);
    } else {
        const uint32_t* d32 = (const uint32_t*)dstraw;
        uint4 m = *(const uint4*)(d32 + (size_t)b * Uu + v0);
        c0 = (m.x != 0); c1 = (m.y != 0); c2 = (m.z != 0); c3 = (m.w != 0);
    }

    int c = c0 + c1 + c2 + c3;
    int incl = c;
#pragma unroll
    for (int off = 1; off < 32; off <<= 1) {
        int y = __shfl_up_sync(0xffffffffu, incl, off);
        if ((t & 31) >= off) incl += y;
    }
    if ((t & 31) == 31) wsum[t >> 5] = incl;
    __syncthreads();
    if (t < 32) {
        int s = wsum[t];
#pragma unroll
        for (int off = 1; off < 32; off <<= 1) {
            int y = __shfl_up_sync(0xffffffffu, s, off);
            if (t >= off) s += y;
        }
        wsum[t] = s;
    }
    __syncthreads();
    int base = (t >= 32) ? wsum[(t >> 5) - 1] : 0;
    int e = base + incl - c;
    if (c0 && e < Ee) g_vlist[b * Ee + e++] = (unsigned short)(v0);
    if (c1 && e < Ee) g_vlist[b * Ee + e++] = (unsigned short)(v0 + 1);
    if (c2 && e < Ee) g_vlist[b * Ee + e++] = (unsigned short)(v0 + 2);
    if (c3 && e < Ee) g_vlist[b * Ee + e++] = (unsigned short)(v0 + 3);
}

// ---------------- scan: one warp streams one full 16KB row of W, emits hits ----------------
__global__ __launch_bounds__(256) void scan_kernel(const float* __restrict__ W) {
    int b    = blockIdx.y;
    int warp = threadIdx.x >> 5;
    int lane = threadIdx.x & 31;
    int e    = blockIdx.x * 8 + warp;

    int v = g_vlist[b * Ee + e];
    const float4* row = (const float4*)(W + ((size_t)b * Uu + v) * Uu);

#pragma unroll 1
    for (int i0 = 0; i0 < 32; i0 += 8) {
        float4 x[8];
#pragma unroll
        for (int j = 0; j < 8; ++j)
            x[j] = __ldcs(&row[(i0 + j) * 32 + lane]);   // streaming: read-once data

#define ORW(v4) (__float_as_uint((v4).x) | __float_as_uint((v4).y) | \
                 __float_as_uint((v4).z) | __float_as_uint((v4).w))
        unsigned any = (ORW(x[0]) | ORW(x[1]) | ORW(x[2]) | ORW(x[3])) |
                       (ORW(x[4]) | ORW(x[5]) | ORW(x[6]) | ORW(x[7]));
        if (any) {
#pragma unroll
            for (int j = 0; j < 8; ++j) {
                float vals[4] = {x[j].x, x[j].y, x[j].z, x[j].w};
#pragma unroll
                for (int k = 0; k < 4; ++k) {
                    if (__float_as_uint(vals[k]) != 0u) {
                        int u  = ((i0 + j) * 32 + lane) * 4 + k;
                        int ut = u >> 6;
                        int pos = atomicAdd(&g_cnt[b * NTILES + ut], 1);
                        if (pos < TCAP)
                            g_list[((size_t)(b * NTILES + ut)) * TCAP + pos] =
                                make_uint2(((unsigned)e << 6) | (unsigned)(u & 63),
                                           __float_as_uint(vals[k]));
                    }
                }
            }
        }
    }
}

// ---------------- accumulate: bucket-by-class, then atomic-free per-warp RMW ----------------
__global__ __launch_bounds__(256) void accum_kernel(
    const float* __restrict__ occ, float* __restrict__ out) {
    __shared__ float s_acc[UT * 132];
    __shared__ float s_rocc[UT];
    __shared__ uint2 s_bkt[8 * BK];
    __shared__ int   s_bcnt[8];

    int b   = blockIdx.y;
    int ut  = blockIdx.x;
    int u0  = ut * UT;
    int tid = threadIdx.x;
    int warp = tid >> 5;     // 0..7
    int lane = tid & 31;
    int n0 = lane * 4;

    if (tid < 8) s_bcnt[tid] = 0;
    for (int i = tid; i < UT * 132; i += 256) s_acc[i] = 0.f;
    if (tid < UT) s_rocc[tid] = 1.0f / occ[(size_t)b * Uu + u0 + tid];
    __syncthreads();

    int cnt = min(g_cnt[b * NTILES + ut], TCAP);
    const uint2* list = &g_list[((size_t)(b * NTILES + ut)) * TCAP];

    // phase 1: bucket entries by u-class (u & 7); atomics only on 8 counters
    for (int i = tid; i < cnt; i += 256) {
        uint2 ent = __ldg(&list[i]);
        int c = ent.x & 7;
        int pos = atomicAdd(&s_bcnt[c], 1);
        if (pos < BK) s_bkt[c * BK + pos] = ent;
    }
    __syncthreads();

    // phase 2: warp w drains bucket w with plain (atomic-free) RMW.
    // class-disjoint u across warps + lane-disjoint n0 within warp = no races.
    // fp-add order within a class may vary run-to-run at ULP level only (<=5 terms).
    {
        const float* ftb = g_ft + (size_t)b * Ee * NF + n0;
        const uint2* bkt = &s_bkt[warp * BK];
        int m = min(s_bcnt[warp], BK);

#define APPLY(ee, ff)                                                     \
        {                                                                 \
            int u = (ee).x & 63;                                          \
            float w = __uint_as_float((ee).y);                            \
            float4* ap = (float4*)&s_acc[u * 132 + n0];                   \
            float4 a = *ap;                                               \
            a.x += w * (ff).x; a.y += w * (ff).y;                         \
            a.z += w * (ff).z; a.w += w * (ff).w;                         \
            *ap = a;                                                      \
        }

        int j = 0;
        for (; j + 4 <= m; j += 4) {     // 4-wide gather batching (MLP=4)
            uint2 e0 = bkt[j], e1 = bkt[j + 1], e2 = bkt[j + 2], e3 = bkt[j + 3];
            float4 f0 = *(const float4*)&ftb[(size_t)(e0.x >> 6) * NF];
            float4 f1 = *(const float4*)&ftb[(size_t)(e1.x >> 6) * NF];
            float4 f2 = *(const float4*)&ftb[(size_t)(e2.x >> 6) * NF];
            float4 f3 = *(const float4*)&ftb[(size_t)(e3.x >> 6) * NF];
            APPLY(e0, f0); APPLY(e1, f1); APPLY(e2, f2); APPLY(e3, f3);
        }
        for (; j < m; ++j) {
            uint2 e0 = bkt[j];
            float4 f0 = *(const float4*)&ftb[(size_t)(e0.x >> 6) * NF];
            APPLY(e0, f0);
        }
    }
    __syncthreads();

    // epilogue: multiply by 1/occ, coalesced store
    int u  = tid & (UT - 1);
    int nb = tid >> 6;          // 0..3
    float r = s_rocc[u];
#pragma unroll
    for (int i = 0; i < (UT * NF / 256); ++i) {   // 32 iters
        int n = 4 * i + nb;
        out[((size_t)(b * NF + n)) * Uu + u0 + u] = s_acc[u * 132 + n] * r;
    }
}

extern "C" void kernel_launch(void* const* d_in, const int* in_sizes, int n_in,
                              void* d_out, int out_size) {
    const float* features          = (const float*)d_in[0];
    const float* unroll_mat        = (const float*)d_in[1];
    const float* occurrences       = (const float*)d_in[2];
    const unsigned char* dst_masks = (const unsigned char*)d_in[3];
    float* out = (float*)d_out;

    build_vlist_kernel<<<Bb, 1024>>>(dst_masks);
    scan_kernel<<<dim3(Ee / 8, Bb), 256>>>(unroll_mat);
    dim3 tg(Ee / 32, NF / 32, Bb);
    transpose_kernel<<<tg, dim3(32, 8)>>>(features);
    accum_kernel<<<dim3(NTILES, Bb), 256>>>(occurrences, out);
}